// round 1
// baseline (speedup 1.0000x reference)
#include <cuda_runtime.h>
#include <math.h>

// Problem constants
#define BD   32      // batch
#define LD   513     // path length
#define DD   8       // input path dim
#define HD   64      // hidden state dim
#define WINW 16      // window
#define NW   32      // windows = (L-1)/WIN
#define WID  128     // vf hidden width
#define OUTD 4
#define NPAIR 28
#define NTH  512

// W3 transposed: gW3T[k*512 + row] = W3[row*128 + k]
__device__ float gW3T[WID * (DD * HD)];

__device__ const int PI_[NPAIR] = {0,0,0,0,0,0,0, 1,1,1,1,1,1, 2,2,2,2,2, 3,3,3,3, 4,4,4, 5,5, 6};
__device__ const int PJ_[NPAIR] = {1,2,3,4,5,6,7, 2,3,4,5,6,7, 3,4,5,6,7, 4,5,6,7, 5,6,7, 6,7, 7};

__device__ __forceinline__ float lipswish(float x, float* dout) {
    float s = 1.0f / (1.0f + expf(-x));
    *dout = 0.909f * s * (1.0f + x * (1.0f - s));
    return 0.909f * x * s;
}

// pair index for i<j in triu(8,1) order
__device__ __forceinline__ int pidx(int i, int j) {
    return (i * (13 - i)) / 2 + j - 1;
}

// One vf_matrix @ g evaluation: yv(64) -> kout(64)
__device__ __forceinline__ void vf_apply(
    int tid, const float* __restrict__ yv, float* __restrict__ kout,
    const float* __restrict__ sW1T, const float* __restrict__ sW2T,
    const float* __restrict__ b1, const float* __restrict__ b2, const float* __restrict__ b3,
    const float* __restrict__ gvec, const float* __restrict__ scm,
    float* sh1, float* ss1, float* sh2, float* ss2,
    float* sf, float* stp, float* sVp, float* sD1, float* sE, float* sp)
{
    // Layer1 forward: pre1[r] = b1[r] + sum_b W1[r][b] y[b]
    if (tid < 128) {
        float a0 = b1[tid], a1 = 0.0f;
        #pragma unroll 8
        for (int bq = 0; bq < 64; bq += 2) {
            a0 += sW1T[bq * 128 + tid] * yv[bq];
            a1 += sW1T[(bq + 1) * 128 + tid] * yv[bq + 1];
        }
        float d;
        sh1[tid] = lipswish(a0 + a1, &d);
        ss1[tid] = d;
    }
    __syncthreads();
    // Layer2 forward
    if (tid < 128) {
        float a0 = b2[tid], a1 = 0.0f;
        #pragma unroll 8
        for (int r = 0; r < 128; r += 2) {
            a0 += sW2T[r * 128 + tid] * sh1[r];
            a1 += sW2T[(r + 1) * 128 + tid] * sh1[r + 1];
        }
        float d;
        sh2[tid] = lipswish(a0 + a1, &d);
        ss2[tid] = d;
    }
    __syncthreads();
    // Layer3 forward: row = tid (512 rows), f = tanh(pre3), tp = 1-f^2
    {
        float a0 = b3[tid], a1 = 0.0f;
        #pragma unroll 8
        for (int k = 0; k < 128; k += 2) {
            a0 += gW3T[k * 512 + tid] * sh2[k];
            a1 += gW3T[(k + 1) * 512 + tid] * sh2[k + 1];
        }
        float f = tanhf(a0 + a1);
        sf[tid] = f;
        stp[tid] = 1.0f - f * f;
    }
    __syncthreads();
    // V' = f^T @ cmat  : Vp[b][j] = sum_i f[i*64+b] * cmat[i][j]
    {
        int bq = tid >> 3, j = tid & 7;
        float acc = 0.0f;
        #pragma unroll
        for (int i = 0; i < 8; i++) acc += sf[i * 64 + bq] * scm[i * 8 + j];
        sVp[bq * 8 + j] = acc;
    }
    __syncthreads();
    // U1' = W1 @ V' ; D1 = s1 * U1'   (thread: r = tid&127, handles j = q and q+4)
    {
        int r = tid & 127, q = tid >> 7;
        float a0 = 0.0f, a1 = 0.0f;
        #pragma unroll 8
        for (int bq = 0; bq < 64; bq++) {
            float w = sW1T[bq * 128 + r];
            a0 += w * sVp[bq * 8 + q];
            a1 += w * sVp[bq * 8 + q + 4];
        }
        float s = ss1[r];
        sD1[r * 8 + q] = s * a0;
        sD1[r * 8 + q + 4] = s * a1;
    }
    __syncthreads();
    // U2' = W2 @ D1 ; E = s2 * U2'  (256 threads: k = tid&127, 4 j's each)
    if (tid < 256) {
        int k = tid & 127, hh = tid >> 7;
        float a0 = 0.f, a1 = 0.f, a2 = 0.f, a3 = 0.f;
        #pragma unroll 4
        for (int r = 0; r < 128; r++) {
            float w = sW2T[r * 128 + k];
            const float4 dv = *(const float4*)(&sD1[r * 8 + 4 * hh]);
            a0 += w * dv.x; a1 += w * dv.y; a2 += w * dv.z; a3 += w * dv.w;
        }
        float s = ss2[k];
        sE[(4 * hh + 0) * 128 + k] = s * a0;
        sE[(4 * hh + 1) * 128 + k] = s * a1;
        sE[(4 * hh + 2) * 128 + k] = s * a2;
        sE[(4 * hh + 3) * 128 + k] = s * a3;
    }
    __syncthreads();
    // diag pass: row = tid, j = row>>6; part[row] = tp[row] * (W3[row,:] . E[:,j])
    {
        int j = tid >> 6;
        const float* Ej = sE + j * 128;
        float a0 = 0.0f, a1 = 0.0f;
        #pragma unroll 8
        for (int k = 0; k < 128; k += 2) {
            a0 += gW3T[k * 512 + tid] * Ej[k];
            a1 += gW3T[(k + 1) * 512 + tid] * Ej[k + 1];
        }
        sp[tid] = stp[tid] * (a0 + a1);
    }
    __syncthreads();
    // combine: k[a] = sum_i g[i] f[i][a] + sum_j part[j*64+a]
    if (tid < 64) {
        float acc = 0.0f;
        #pragma unroll
        for (int j = 0; j < 8; j++) acc += sp[j * 64 + tid];
        #pragma unroll
        for (int i = 0; i < 8; i++) acc += gvec[i] * sf[i * 64 + tid];
        kout[tid] = acc;
    }
    __syncthreads();
}

extern __shared__ float sm[];

__global__ void __launch_bounds__(NTH, 1) ncde_kernel(
    const float* __restrict__ cv,
    const float* __restrict__ Wi1, const float* __restrict__ bi1,
    const float* __restrict__ Wi2, const float* __restrict__ bi2,
    const float* __restrict__ W1, const float* __restrict__ b1,
    const float* __restrict__ W2, const float* __restrict__ b2,
    const float* __restrict__ W3, const float* __restrict__ b3,
    const float* __restrict__ Wr, const float* __restrict__ br,
    const float* __restrict__ shiftp,
    float* __restrict__ out)
{
    const int tid = threadIdx.x;
    const int b = blockIdx.x;

    float* sW1T = sm;                 // 8192
    float* sW2T = sW1T + 8192;        // 16384 (reused as increment scratch at init)
    float* sG   = sW2T + 16384;       // 32*36 = 1152
    float* sy   = sG + 1152;          // 64
    float* symid= sy + 64;            // 64
    float* sk1  = symid + 64;         // 64
    float* skout= sk1 + 64;           // 64
    float* scm  = skout + 64;         // 64
    float* sh1  = scm + 64;           // 128
    float* ss1  = sh1 + 128;          // 128
    float* sh2  = ss1 + 128;          // 128
    float* ss2  = sh2 + 128;          // 128
    float* sf   = ss2 + 128;          // 512
    float* stp  = sf + 512;           // 512
    float* sVp  = stp + 512;          // 512
    float* sD1  = sVp + 512;          // 1024
    float* sE   = sD1 + 1024;         // 1024
    float* sp   = sE + 1024;          // 512

    const float dt = (float)WINW / (float)(LD - 1);  // 0.03125
    const float inv_dt = 1.0f / dt;

    // Load W1^T into smem: sW1T[b*128 + r] = W1[r*64 + b]
    for (int idx = tid; idx < 128 * 64; idx += NTH) {
        int bq = idx >> 7, r = idx & 127;
        sW1T[idx] = W1[r * 64 + bq];
    }
    // Transpose W3 into global scratch (every CTA writes identical values)
    for (int idx = tid; idx < 128 * 512; idx += NTH) {
        int k = idx >> 9, row = idx & 511;
        gW3T[idx] = W3[row * 128 + k];
    }
    // Path increments into scratch (W2 region, loaded later)
    const float* cvb = cv + (size_t)b * LD * DD;
    for (int idx = tid; idx < 512 * 8; idx += NTH) {
        sW2T[idx] = cvb[idx + 8] - cvb[idx];
    }
    __syncthreads();

    // Window log-signatures -> sG[w*36 + c], already divided by dt
    {
        const float* sInc = sW2T;
        if (tid < NW * NPAIR) {
            int w = tid / NPAIR, p = tid % NPAIR;
            int i = PI_[p], j = PJ_[p];
            float acc = 0.f, pi = 0.f, pj = 0.f;
            const float* base = sInc + w * 16 * 8;
            #pragma unroll
            for (int s = 0; s < 16; s++) {
                float ii = base[s * 8 + i], jj = base[s * 8 + j];
                acc += pi * jj - pj * ii;
                pi += ii; pj += jj;
            }
            sG[w * 36 + 8 + p] = 0.5f * acc * inv_dt;
        }
        if (tid < NW * 8) {
            int w = tid >> 3, d2 = tid & 7;
            sG[w * 36 + d2] = (cvb[(16 * w + 16) * 8 + d2] - cvb[16 * w * 8 + d2]) * inv_dt;
        }
    }
    __syncthreads();

    // Load W2^T into smem (overwrites increment scratch)
    for (int idx = tid; idx < 128 * 128; idx += NTH) {
        int r = idx >> 7, k = idx & 127;
        sW2T[idx] = W2[k * 128 + r];
    }

    // y0 = Wi2 @ lipswish(Wi1 @ v0 + bi1) + bi2  (uses sh1 as temp)
    if (tid < 64) {
        float acc = bi1[tid];
        #pragma unroll
        for (int d2 = 0; d2 < 8; d2++) acc += Wi1[tid * 8 + d2] * cvb[d2];
        float dd;
        sh1[tid] = lipswish(acc, &dd);
    }
    __syncthreads();
    if (tid < 64) {
        float acc = bi2[tid];
        #pragma unroll 8
        for (int h = 0; h < 64; h++) acc += Wi2[tid * 64 + h] * sh1[h];
        sy[tid] = acc;
    }
    __syncthreads();

    const float shiftv = *shiftp;
    // readout row 0
    if (tid < 4) {
        float acc = br[tid] + shiftv;
        #pragma unroll 8
        for (int a = 0; a < 64; a++) acc += Wr[tid * 64 + a] * sy[a];
        out[b * (NW + 1) * OUTD + tid] = acc;
    }

    // Main Heun loop over windows (sequential)
    for (int n = 0; n < NW; n++) {
        const float* gvec = sG + n * 36;
        // cmat (antisymmetric 8x8 from levy part of g)
        if (tid < 64) {
            int i = tid >> 3, j = tid & 7;
            float v = 0.0f;
            if (i < j) v = gvec[8 + pidx(i, j)];
            else if (i > j) v = -gvec[8 + pidx(j, i)];
            scm[tid] = v;
        }
        __syncthreads();

        vf_apply(tid, sy, sk1, sW1T, sW2T, b1, b2, b3, gvec, scm,
                 sh1, ss1, sh2, ss2, sf, stp, sVp, sD1, sE, sp);

        if (tid < 64) symid[tid] = sy[tid] + dt * sk1[tid];
        __syncthreads();

        vf_apply(tid, symid, skout, sW1T, sW2T, b1, b2, b3, gvec, scm,
                 sh1, ss1, sh2, ss2, sf, stp, sVp, sD1, sE, sp);

        if (tid < 64) sy[tid] = sy[tid] + 0.5f * dt * (sk1[tid] + skout[tid]);
        __syncthreads();

        // readout row n+1
        if (tid < 4) {
            float acc = br[tid] + shiftv;
            #pragma unroll 8
            for (int a = 0; a < 64; a++) acc += Wr[tid * 64 + a] * sy[a];
            out[b * (NW + 1) * OUTD + (n + 1) * OUTD + tid] = acc;
        }
    }
}

extern "C" void kernel_launch(void* const* d_in, const int* in_sizes, int n_in,
                              void* d_out, int out_size) {
    (void)in_sizes; (void)n_in; (void)out_size;
    const size_t smem = 30656 * sizeof(float);  // 122,624 B
    cudaFuncSetAttribute(ncde_kernel, cudaFuncAttributeMaxDynamicSharedMemorySize, (int)smem);
    ncde_kernel<<<BD, NTH, smem>>>(
        (const float*)d_in[0],
        (const float*)d_in[1], (const float*)d_in[2],
        (const float*)d_in[3], (const float*)d_in[4],
        (const float*)d_in[5], (const float*)d_in[6],
        (const float*)d_in[7], (const float*)d_in[8],
        (const float*)d_in[9], (const float*)d_in[10],
        (const float*)d_in[11], (const float*)d_in[12],
        (const float*)d_in[13],
        (float*)d_out);
}

// round 2
// speedup vs baseline: 1.1724x; 1.1724x over previous
#include <cuda_runtime.h>

typedef unsigned long long u64;

#define BD   32
#define LD   513
#define DD   8
#define HD   64
#define WINW 16
#define NW   32
#define OUTD 4
#define NPAIR 28
#define NTH  512

// Pair-packed W3: gW3P[k2*512 + row] = (W3[row][2k2], W3[row][2k2+1])
__device__ u64 gW3P[64 * 512];

__device__ const signed char PI_[NPAIR] = {0,0,0,0,0,0,0, 1,1,1,1,1,1, 2,2,2,2,2, 3,3,3,3, 4,4,4, 5,5, 6};
__device__ const signed char PJ_[NPAIR] = {1,2,3,4,5,6,7, 2,3,4,5,6,7, 3,4,5,6,7, 4,5,6,7, 5,6,7, 6,7, 7};

// ---------- fast math helpers ----------
__device__ __forceinline__ float ex2f(float x){ float y; asm("ex2.approx.f32 %0, %1;" : "=f"(y) : "f"(x)); return y; }
__device__ __forceinline__ float rcpf(float x){ float y; asm("rcp.approx.f32 %0, %1;" : "=f"(y) : "f"(x)); return y; }
__device__ __forceinline__ float sigf(float x){ return rcpf(1.0f + ex2f(-1.4426950408889634f * x)); }
__device__ __forceinline__ float tanh_fast(float x){
    float t = ex2f(2.8853900817779268f * x);
    return 1.0f - 2.0f * rcpf(t + 1.0f);
}
__device__ __forceinline__ float lipswish(float x, float* dout){
    float s = sigf(x);
    *dout = 0.909f * s * fmaf(x, 1.0f - s, 1.0f);
    return 0.909f * x * s;
}

// ---------- packed f32x2 helpers ----------
__device__ __forceinline__ u64 f2u(float x, float y){ u64 v; asm("mov.b64 %0, {%1, %2};" : "=l"(v) : "f"(x), "f"(y)); return v; }
__device__ __forceinline__ float hsum2(u64 v){ float a, b; asm("mov.b64 {%0, %1}, %2;" : "=f"(a), "=f"(b) : "l"(v)); return a + b; }
__device__ __forceinline__ u64 fma2(u64 a, u64 b, u64 c){ u64 d; asm("fma.rn.f32x2 %0, %1, %2, %3;" : "=l"(d) : "l"(a), "l"(b), "l"(c)); return d; }

__device__ __forceinline__ int pidx(int i, int j) { return (i * (13 - i)) / 2 + j - 1; }

// One vf_matrix @ g evaluation: yv(64) -> kout(64). All pointers pre-offset.
__device__ __forceinline__ void vf_apply(
    int tid, const float* __restrict__ yv, float* __restrict__ kout,
    const u64* __restrict__ W1P, const u64* __restrict__ W2P,
    const float* __restrict__ b1, const float* __restrict__ b2, const float* __restrict__ b3,
    const float* __restrict__ gvec, const float* __restrict__ scm,
    float* sh1, float* ss1, float* sh2, float* ss2,
    float* sf, float* stp, float* sVpT, float* sD1T, float* sE, float* sp)
{
    const u64* Y2  = (const u64*)yv;
    const u64* H1  = (const u64*)sh1;
    const u64* H2  = (const u64*)sh2;

    // ---- L1 forward: pre1[r] = b1[r] + W1[r,:] . y ----
    if (tid < 128) {
        const int r = tid;
        u64 a0 = 0ull, a1 = 0ull;
        #pragma unroll
        for (int b2i = 0; b2i < 32; b2i += 2) {
            a0 = fma2(W1P[b2i * 128 + r],       Y2[b2i],     a0);
            a1 = fma2(W1P[(b2i + 1) * 128 + r], Y2[b2i + 1], a1);
        }
        float pre = b1[r] + hsum2(a0) + hsum2(a1);
        float d; sh1[r] = lipswish(pre, &d); ss1[r] = d;
    }
    __syncthreads();

    // ---- L2 forward ----
    if (tid < 128) {
        const int k = tid;
        u64 a0 = 0ull, a1 = 0ull;
        #pragma unroll 16
        for (int r2 = 0; r2 < 64; r2 += 2) {
            a0 = fma2(W2P[r2 * 128 + k],       H1[r2],     a0);
            a1 = fma2(W2P[(r2 + 1) * 128 + k], H1[r2 + 1], a1);
        }
        float pre = b2[k] + hsum2(a0) + hsum2(a1);
        float d; sh2[k] = lipswish(pre, &d); ss2[k] = d;
    }
    __syncthreads();

    // ---- L3 forward: row = tid (512 rows) ----
    {
        const int row = tid;
        u64 a0 = 0ull, a1 = 0ull;
        #pragma unroll 16
        for (int k2 = 0; k2 < 64; k2 += 2) {
            a0 = fma2(gW3P[k2 * 512 + row],       H2[k2],     a0);
            a1 = fma2(gW3P[(k2 + 1) * 512 + row], H2[k2 + 1], a1);
        }
        float f = tanh_fast(b3[row] + hsum2(a0) + hsum2(a1));
        sf[row] = f;
        stp[row] = 1.0f - f * f;
    }
    __syncthreads();

    // ---- VpT[j][b] = sum_i f[i*64+b] * cmat[i][j] ----
    {
        const int j = tid >> 6, bq = tid & 63;
        float acc = 0.0f;
        #pragma unroll
        for (int i = 0; i < 8; i++) acc += sf[i * 64 + bq] * scm[i * 8 + j];
        sVpT[tid] = acc;   // sVpT[j*64 + bq]
    }
    __syncthreads();

    // ---- U1': D1T[j][r] = s1[r] * (W1[r,:] . VpT[j,:]), j = q and q+4 ----
    {
        const int r = tid & 127, q = tid >> 7;
        const u64* VPT2 = (const u64*)sVpT;
        u64 a0 = 0ull, a1 = 0ull;
        #pragma unroll 16
        for (int b2i = 0; b2i < 32; b2i++) {
            u64 w = W1P[b2i * 128 + r];
            a0 = fma2(w, VPT2[q * 32 + b2i],       a0);
            a1 = fma2(w, VPT2[(q + 4) * 32 + b2i], a1);
        }
        float s = ss1[r];
        sD1T[q * 128 + r]       = s * hsum2(a0);
        sD1T[(q + 4) * 128 + r] = s * hsum2(a1);
    }
    __syncthreads();

    // ---- U2': E[j][k] = s2[k] * (W2[k,:] . D1T[j,:]), j = hh and hh+4 ----
    {
        const int k = tid & 127, hh = tid >> 7;
        const u64* D1T2 = (const u64*)sD1T;
        u64 a0 = 0ull, a1 = 0ull;
        #pragma unroll 16
        for (int r2 = 0; r2 < 64; r2++) {
            u64 w = W2P[r2 * 128 + k];
            a0 = fma2(w, D1T2[hh * 64 + r2],       a0);
            a1 = fma2(w, D1T2[(hh + 4) * 64 + r2], a1);
        }
        float s = ss2[k];
        sE[hh * 128 + k]       = s * hsum2(a0);
        sE[(hh + 4) * 128 + k] = s * hsum2(a1);
    }
    __syncthreads();

    // ---- diag pass: row = tid, j = row>>6 ----
    {
        const int row = tid, j = row >> 6;
        const u64* E2 = (const u64*)sE;
        u64 a0 = 0ull, a1 = 0ull;
        #pragma unroll 16
        for (int k2 = 0; k2 < 64; k2 += 2) {
            a0 = fma2(gW3P[k2 * 512 + row],       E2[j * 64 + k2],     a0);
            a1 = fma2(gW3P[(k2 + 1) * 512 + row], E2[j * 64 + k2 + 1], a1);
        }
        sp[row] = stp[row] * (hsum2(a0) + hsum2(a1));
    }
    __syncthreads();

    // ---- combine ----
    if (tid < 64) {
        float acc = 0.0f;
        #pragma unroll
        for (int j = 0; j < 8; j++) acc += sp[j * 64 + tid];
        #pragma unroll
        for (int i = 0; i < 8; i++) acc += gvec[i] * sf[i * 64 + tid];
        kout[tid] = acc;
    }
    __syncthreads();
}

extern __shared__ float sm[];

__global__ void __launch_bounds__(NTH, 1) ncde_kernel(
    const float* __restrict__ cv,
    const float* __restrict__ Wi1, const float* __restrict__ bi1,
    const float* __restrict__ Wi2, const float* __restrict__ bi2,
    const float* __restrict__ W1, const float* __restrict__ b1,
    const float* __restrict__ W2, const float* __restrict__ b2,
    const float* __restrict__ W3, const float* __restrict__ b3,
    const float* __restrict__ Wr, const float* __restrict__ br,
    const float* __restrict__ shiftp,
    float* __restrict__ out)
{
    const int tid = threadIdx.x;
    const int b = blockIdx.x;

    u64*   W1P  = (u64*)sm;            // 4096 u64 = 8192 floats
    u64*   W2P  = (u64*)(sm + 8192);   // 8192 u64 = 16384 floats
    float* sG   = sm + 24576;          // 1152
    float* sy   = sm + 25728;          // 64
    float* symid= sm + 25792;          // 64
    float* sk1  = sm + 25856;          // 64
    float* sk2  = sm + 25920;          // 64
    float* scm  = sm + 25984;          // 64
    float* sh1  = sm + 26048;          // 128
    float* ss1  = sm + 26176;          // 128
    float* sh2  = sm + 26304;          // 128
    float* ss2  = sm + 26432;          // 128
    float* sf   = sm + 26560;          // 512
    float* stp  = sm + 27072;          // 512
    float* sVpT = sm + 27584;          // 512
    float* sD1T = sm + 28096;          // 1024
    float* sE   = sm + 29120;          // 1024
    float* sp   = sm + 30144;          // 512  -> total 30656 floats

    const float dt = (float)WINW / (float)(LD - 1);
    const float inv_dt = 1.0f / dt;

    // ---- init: pair-packed W1 into smem ----
    for (int idx = tid; idx < 32 * 128; idx += NTH) {
        int b2i = idx >> 7, r = idx & 127;
        W1P[idx] = f2u(W1[r * 64 + 2 * b2i], W1[r * 64 + 2 * b2i + 1]);
    }
    // ---- pair-packed W3 into global scratch (all CTAs write identical data) ----
    for (int idx = tid; idx < 64 * 512; idx += NTH) {
        int k2 = idx >> 9, row = idx & 511;
        gW3P[idx] = f2u(W3[row * 128 + 2 * k2], W3[row * 128 + 2 * k2 + 1]);
    }
    // ---- path increments into scratch (W2P region, loaded afterwards) ----
    const float* cvb = cv + (size_t)b * LD * DD;
    float* sInc = sm + 8192;
    for (int idx = tid; idx < 512 * 8; idx += NTH) {
        sInc[idx] = cvb[idx + 8] - cvb[idx];
    }
    __syncthreads();

    // ---- window log-signatures (pre-divided by dt) ----
    for (int idx = tid; idx < NW * NPAIR; idx += NTH) {
        int w = idx / NPAIR, p = idx % NPAIR;
        int i = PI_[p], j = PJ_[p];
        float acc = 0.f, pi = 0.f, pj = 0.f;
        const float* base = sInc + w * 16 * 8;
        #pragma unroll
        for (int s = 0; s < 16; s++) {
            float ii = base[s * 8 + i], jj = base[s * 8 + j];
            acc += pi * jj - pj * ii;
            pi += ii; pj += jj;
        }
        sG[w * 36 + 8 + p] = 0.5f * acc * inv_dt;
    }
    for (int idx = tid; idx < NW * 8; idx += NTH) {
        int w = idx >> 3, d2 = idx & 7;
        sG[w * 36 + d2] = (cvb[(16 * w + 16) * 8 + d2] - cvb[16 * w * 8 + d2]) * inv_dt;
    }
    // y0 layer1 (temp in sh1)
    if (tid < 64) {
        float acc = bi1[tid];
        #pragma unroll
        for (int d2 = 0; d2 < 8; d2++) acc += Wi1[tid * 8 + d2] * cvb[d2];
        float dd;
        sh1[tid] = lipswish(acc, &dd);
    }
    __syncthreads();

    // ---- pair-packed W2 into smem (overwrites increments) ----
    for (int idx = tid; idx < 64 * 128; idx += NTH) {
        int r2 = idx >> 7, k = idx & 127;
        W2P[idx] = f2u(W2[k * 128 + 2 * r2], W2[k * 128 + 2 * r2 + 1]);
    }
    // y0 layer2
    if (tid < 64) {
        float acc = bi2[tid];
        #pragma unroll 8
        for (int h = 0; h < 64; h++) acc += Wi2[tid * 64 + h] * sh1[h];
        sy[tid] = acc;
    }
    __syncthreads();

    const float shiftv = *shiftp;
    if (tid < 4) {
        float acc = br[tid] + shiftv;
        #pragma unroll 8
        for (int a = 0; a < 64; a++) acc += Wr[tid * 64 + a] * sy[a];
        out[b * (NW + 1) * OUTD + tid] = acc;
    }

    // ---- main Heun loop ----
    for (int n = 0; n < NW; n++) {
        const float* gvec = sG + n * 36;
        if (tid < 64) {
            int i = tid >> 3, j = tid & 7;
            float v = 0.0f;
            if (i < j) v = gvec[8 + pidx(i, j)];
            else if (i > j) v = -gvec[8 + pidx(j, i)];
            scm[tid] = v;
        }
        __syncthreads();

        vf_apply(tid, sy, sk1, W1P, W2P, b1, b2, b3, gvec, scm,
                 sh1, ss1, sh2, ss2, sf, stp, sVpT, sD1T, sE, sp);

        if (tid < 64) symid[tid] = sy[tid] + dt * sk1[tid];
        __syncthreads();

        vf_apply(tid, symid, sk2, W1P, W2P, b1, b2, b3, gvec, scm,
                 sh1, ss1, sh2, ss2, sf, stp, sVpT, sD1T, sE, sp);

        if (tid < 64) sy[tid] = sy[tid] + 0.5f * dt * (sk1[tid] + sk2[tid]);
        __syncthreads();

        if (tid < 4) {
            float acc = br[tid] + shiftv;
            #pragma unroll 8
            for (int a = 0; a < 64; a++) acc += Wr[tid * 64 + a] * sy[a];
            out[b * (NW + 1) * OUTD + (n + 1) * OUTD + tid] = acc;
        }
        __syncthreads();
    }
}

extern "C" void kernel_launch(void* const* d_in, const int* in_sizes, int n_in,
                              void* d_out, int out_size) {
    (void)in_sizes; (void)n_in; (void)out_size;
    const size_t smem = 30656 * sizeof(float);  // 122,624 B
    cudaFuncSetAttribute(ncde_kernel, cudaFuncAttributeMaxDynamicSharedMemorySize, (int)smem);
    ncde_kernel<<<BD, NTH, smem>>>(
        (const float*)d_in[0],
        (const float*)d_in[1], (const float*)d_in[2],
        (const float*)d_in[3], (const float*)d_in[4],
        (const float*)d_in[5], (const float*)d_in[6],
        (const float*)d_in[7], (const float*)d_in[8],
        (const float*)d_in[9], (const float*)d_in[10],
        (const float*)d_in[11], (const float*)d_in[12],
        (const float*)d_in[13],
        (float*)d_out);
}

// round 3
// speedup vs baseline: 1.7337x; 1.4789x over previous
#include <cuda_runtime.h>

typedef unsigned long long u64;

#define BD   32
#define LD   513
#define DD   8
#define HD   64
#define WINW 16
#define NW   32
#define OUTD 4
#define NPAIR 28
#define NTH  512

// W3 quad-packed: gW3Q[q*512 + row] = W3[row][4q..4q+3]  (q = 0..15)
__device__ ulonglong2 gW3Q[16 * 512];

__device__ const signed char PI_[NPAIR] = {0,0,0,0,0,0,0, 1,1,1,1,1,1, 2,2,2,2,2, 3,3,3,3, 4,4,4, 5,5, 6};
__device__ const signed char PJ_[NPAIR] = {1,2,3,4,5,6,7, 2,3,4,5,6,7, 3,4,5,6,7, 4,5,6,7, 5,6,7, 6,7, 7};

// ---------- fast math ----------
__device__ __forceinline__ float ex2f(float x){ float y; asm("ex2.approx.f32 %0, %1;" : "=f"(y) : "f"(x)); return y; }
__device__ __forceinline__ float rcpf(float x){ float y; asm("rcp.approx.f32 %0, %1;" : "=f"(y) : "f"(x)); return y; }
__device__ __forceinline__ float sigf(float x){ return rcpf(1.0f + ex2f(-1.4426950408889634f * x)); }
__device__ __forceinline__ float tanh_fast(float x){
    float t = ex2f(2.8853900817779268f * x);
    return 1.0f - 2.0f * rcpf(t + 1.0f);
}
__device__ __forceinline__ float lipswish(float x, float* dout){
    float s = sigf(x);
    *dout = 0.909f * s * fmaf(x, 1.0f - s, 1.0f);
    return 0.909f * x * s;
}

// ---------- packed f32x2 ----------
__device__ __forceinline__ u64 f2u(float x, float y){ u64 v; asm("mov.b64 %0, {%1, %2};" : "=l"(v) : "f"(x), "f"(y)); return v; }
__device__ __forceinline__ float hsum2(u64 v){ float a, b; asm("mov.b64 {%0, %1}, %2;" : "=f"(a), "=f"(b) : "l"(v)); return a + b; }
__device__ __forceinline__ u64 fma2(u64 a, u64 b, u64 c){ u64 d; asm("fma.rn.f32x2 %0, %1, %2, %3;" : "=l"(d) : "l"(a), "l"(b), "l"(c)); return d; }

__device__ __forceinline__ int pidx(int i, int j) { return (i * (13 - i)) / 2 + j - 1; }

struct Smem {
    ulonglong2 W1Q[16 * 128];   // 32 KB: W1Q[b4*128+r] = W1[r][4b4..+3]
    ulonglong2 W2Q[32 * 128];   // 64 KB: W2Q[r4*128+k] = W2[k][4r4..+3]
    float sG[NW * 36];
    float sy[64], symid[64], sk1[64], scm[64];
    float sh1[128], ss1[128], sh2[128], ss2[128];
    float sf[512], stp[512];
    float sVpT[512];            // [j][b]
    float sD1F[1024];           // [j][r]
    float sEF[1024];            // [j][k]
    float sp[512];
    float sPart[4096];          // partial-reduce buffer; also sInc at init
};

// PH = 1: first Heun stage (writes sk1, symid). PH = 2: second stage (updates sy).
template<int PH>
__device__ __forceinline__ void vf_apply(
    Smem* S, int tid, const float* __restrict__ yv,
    const float* __restrict__ b1, const float* __restrict__ b2, const float* __restrict__ b3,
    const float* __restrict__ gvec, float dt)
{
    // ---- L1 forward (128 threads) ----
    if (tid < 128) {
        const int r = tid;
        u64 a0 = 0ull, a1 = 0ull;
        #pragma unroll
        for (int b4 = 0; b4 < 16; b4++) {
            ulonglong2 w = S->W1Q[b4 * 128 + r];
            ulonglong2 yq = *(const ulonglong2*)(yv + 4 * b4);
            a0 = fma2(w.x, yq.x, a0);
            a1 = fma2(w.y, yq.y, a1);
        }
        float pre = b1[r] + hsum2(a0) + hsum2(a1);
        float d; S->sh1[r] = lipswish(pre, &d); S->ss1[r] = d;
    }
    __syncthreads();

    // ---- L2 forward (128 threads) ----
    if (tid < 128) {
        const int k = tid;
        u64 a0 = 0ull, a1 = 0ull;
        #pragma unroll 8
        for (int r4 = 0; r4 < 32; r4++) {
            ulonglong2 w = S->W2Q[r4 * 128 + k];
            ulonglong2 h = *(const ulonglong2*)(S->sh1 + 4 * r4);
            a0 = fma2(w.x, h.x, a0);
            a1 = fma2(w.y, h.y, a1);
        }
        float pre = b2[k] + hsum2(a0) + hsum2(a1);
        float d; S->sh2[k] = lipswish(pre, &d); S->ss2[k] = d;
    }
    __syncthreads();

    // ---- L3 forward (512 threads, row = tid) ----
    {
        const int row = tid;
        u64 a0 = 0ull, a1 = 0ull;
        #pragma unroll 4
        for (int q = 0; q < 16; q++) {
            ulonglong2 w = gW3Q[q * 512 + row];
            ulonglong2 h = *(const ulonglong2*)(S->sh2 + 4 * q);
            a0 = fma2(w.x, h.x, a0);
            a1 = fma2(w.y, h.y, a1);
        }
        float f = tanh_fast(b3[row] + hsum2(a0) + hsum2(a1));
        S->sf[row] = f;
        S->stp[row] = 1.0f - f * f;
    }
    __syncthreads();

    // ---- Vp: sVpT[j][b] = sum_i f[i*64+b] * cmat[i][j] ----
    {
        const int j = tid >> 6, bq = tid & 63;
        float acc = 0.0f;
        #pragma unroll
        for (int i = 0; i < 8; i++) acc += S->sf[i * 64 + bq] * S->scm[i * 8 + j];
        S->sVpT[j * 64 + bq] = acc;
    }
    __syncthreads();

    // ---- U1' partial: 512 threads (c = chunk over b, r) ----
    {
        const int c = tid >> 7, r = tid & 127;
        u64 acc[8] = {0ull,0ull,0ull,0ull,0ull,0ull,0ull,0ull};
        #pragma unroll
        for (int ib = 0; ib < 4; ib++) {
            const int b4 = 4 * c + ib;
            ulonglong2 w = S->W1Q[b4 * 128 + r];
            #pragma unroll
            for (int j = 0; j < 8; j++) {
                ulonglong2 d = *(const ulonglong2*)(S->sVpT + j * 64 + 4 * b4);
                acc[j] = fma2(w.x, d.x, acc[j]);
                acc[j] = fma2(w.y, d.y, acc[j]);
            }
        }
        #pragma unroll
        for (int j = 0; j < 8; j++) S->sPart[c * 1024 + j * 128 + r] = hsum2(acc[j]);
    }
    __syncthreads();

    // ---- U1' reduce -> D1F[j][r] ----
    {
        const int j = tid >> 7, r = tid & 127;
        const float s = S->ss1[r];
        #pragma unroll
        for (int jj = j; jj < 8; jj += 4) {
            float v = S->sPart[jj * 128 + r] + S->sPart[1024 + jj * 128 + r]
                    + S->sPart[2048 + jj * 128 + r] + S->sPart[3072 + jj * 128 + r];
            S->sD1F[jj * 128 + r] = s * v;
        }
    }
    __syncthreads();

    // ---- U2' partial: 512 threads (c = chunk over r, k) ----
    {
        const int c = tid >> 7, k = tid & 127;
        u64 acc[8] = {0ull,0ull,0ull,0ull,0ull,0ull,0ull,0ull};
        #pragma unroll
        for (int ir = 0; ir < 8; ir++) {
            const int r4 = 8 * c + ir;
            ulonglong2 w = S->W2Q[r4 * 128 + k];
            #pragma unroll
            for (int j = 0; j < 8; j++) {
                ulonglong2 d = *(const ulonglong2*)(S->sD1F + j * 128 + 4 * r4);
                acc[j] = fma2(w.x, d.x, acc[j]);
                acc[j] = fma2(w.y, d.y, acc[j]);
            }
        }
        #pragma unroll
        for (int j = 0; j < 8; j++) S->sPart[c * 1024 + j * 128 + k] = hsum2(acc[j]);
    }
    __syncthreads();

    // ---- U2' reduce -> EF[j][k] ----
    {
        const int j = tid >> 7, k = tid & 127;
        const float s = S->ss2[k];
        #pragma unroll
        for (int jj = j; jj < 8; jj += 4) {
            float v = S->sPart[jj * 128 + k] + S->sPart[1024 + jj * 128 + k]
                    + S->sPart[2048 + jj * 128 + k] + S->sPart[3072 + jj * 128 + k];
            S->sEF[jj * 128 + k] = s * v;
        }
    }
    __syncthreads();

    // ---- diag pass: row = tid, j = row >> 6 ----
    {
        const int row = tid, j = row >> 6;
        const float* Ej = S->sEF + j * 128;
        u64 a0 = 0ull, a1 = 0ull;
        #pragma unroll 4
        for (int q = 0; q < 16; q++) {
            ulonglong2 w = gW3Q[q * 512 + row];
            ulonglong2 e = *(const ulonglong2*)(Ej + 4 * q);
            a0 = fma2(w.x, e.x, a0);
            a1 = fma2(w.y, e.y, a1);
        }
        S->sp[row] = S->stp[row] * (hsum2(a0) + hsum2(a1));
    }
    __syncthreads();

    // ---- combine + Heun update ----
    if (tid < 64) {
        float acc = 0.0f;
        #pragma unroll
        for (int j = 0; j < 8; j++) acc += S->sp[j * 64 + tid];
        #pragma unroll
        for (int i = 0; i < 8; i++) acc += gvec[i] * S->sf[i * 64 + tid];
        if (PH == 1) {
            S->sk1[tid] = acc;
            S->symid[tid] = S->sy[tid] + dt * acc;
        } else {
            S->sy[tid] = S->sy[tid] + 0.5f * dt * (S->sk1[tid] + acc);
        }
    }
    __syncthreads();
}

extern __shared__ float smraw[];

__global__ void __launch_bounds__(NTH, 1) ncde_kernel(
    const float* __restrict__ cv,
    const float* __restrict__ Wi1, const float* __restrict__ bi1,
    const float* __restrict__ Wi2, const float* __restrict__ bi2,
    const float* __restrict__ W1, const float* __restrict__ b1,
    const float* __restrict__ W2, const float* __restrict__ b2,
    const float* __restrict__ W3, const float* __restrict__ b3,
    const float* __restrict__ Wr, const float* __restrict__ br,
    const float* __restrict__ shiftp,
    float* __restrict__ out)
{
    Smem* S = (Smem*)smraw;
    const int tid = threadIdx.x;
    const int b = blockIdx.x;

    const float dt = (float)WINW / (float)(LD - 1);
    const float inv_dt = 1.0f / dt;

    // ---- init: quad-pack weights ----
    for (int idx = tid; idx < 16 * 128; idx += NTH) {
        int b4 = idx >> 7, r = idx & 127;
        float4 v = ((const float4*)W1)[r * 16 + b4];
        ulonglong2 q; q.x = f2u(v.x, v.y); q.y = f2u(v.z, v.w);
        S->W1Q[idx] = q;
    }
    for (int idx = tid; idx < 32 * 128; idx += NTH) {
        int r4 = idx >> 7, k = idx & 127;
        float4 v = ((const float4*)W2)[k * 32 + r4];
        ulonglong2 q; q.x = f2u(v.x, v.y); q.y = f2u(v.z, v.w);
        S->W2Q[idx] = q;
    }
    for (int idx = tid; idx < 16 * 512; idx += NTH) {
        int q16 = idx >> 9, row = idx & 511;
        float4 v = ((const float4*)W3)[row * 32 + q16];
        ulonglong2 q; q.x = f2u(v.x, v.y); q.y = f2u(v.z, v.w);
        gW3Q[idx] = q;
    }
    // path increments into sPart
    const float* cvb = cv + (size_t)b * LD * DD;
    for (int idx = tid; idx < 512 * 8; idx += NTH) {
        S->sPart[idx] = cvb[idx + 8] - cvb[idx];
    }
    __syncthreads();

    // ---- window log-signatures (pre-divided by dt) ----
    const float* sInc = S->sPart;
    for (int idx = tid; idx < NW * NPAIR; idx += NTH) {
        int w = idx / NPAIR, p = idx % NPAIR;
        int i = PI_[p], j = PJ_[p];
        float acc = 0.f, pi = 0.f, pj = 0.f;
        const float* base = sInc + w * 16 * 8;
        #pragma unroll
        for (int s = 0; s < 16; s++) {
            float ii = base[s * 8 + i], jj = base[s * 8 + j];
            acc += pi * jj - pj * ii;
            pi += ii; pj += jj;
        }
        S->sG[w * 36 + 8 + p] = 0.5f * acc * inv_dt;
    }
    for (int idx = tid; idx < NW * 8; idx += NTH) {
        int w = idx >> 3, d2 = idx & 7;
        S->sG[w * 36 + d2] = (cvb[(16 * w + 16) * 8 + d2] - cvb[16 * w * 8 + d2]) * inv_dt;
    }
    // y0 layer1 into sh1
    if (tid < 64) {
        float acc = bi1[tid];
        #pragma unroll
        for (int d2 = 0; d2 < 8; d2++) acc += Wi1[tid * 8 + d2] * cvb[d2];
        float dd;
        S->sh1[tid] = lipswish(acc, &dd);
    }
    __syncthreads();
    // y0 layer2
    if (tid < 64) {
        float acc = bi2[tid];
        #pragma unroll 8
        for (int h = 0; h < 64; h++) acc += Wi2[tid * 64 + h] * S->sh1[h];
        S->sy[tid] = acc;
    }
    __syncthreads();

    const float shiftv = *shiftp;

    // ---- main Heun loop ----
    for (int n = 0; n < NW; n++) {
        const float* gvec = S->sG + n * 36;
        // top phase: cmat (tid<64) + readout of current y at index n (tid 64..67)
        if (tid < 64) {
            int i = tid >> 3, j = tid & 7;
            float v = 0.0f;
            if (i < j) v = gvec[8 + pidx(i, j)];
            else if (i > j) v = -gvec[8 + pidx(j, i)];
            S->scm[tid] = v;
        } else if (tid < 68) {
            int rt = tid - 64;
            float acc = br[rt] + shiftv;
            #pragma unroll 8
            for (int a = 0; a < 64; a++) acc += Wr[rt * 64 + a] * S->sy[a];
            out[b * (NW + 1) * OUTD + n * OUTD + rt] = acc;
        }
        __syncthreads();

        vf_apply<1>(S, tid, S->sy,    b1, b2, b3, gvec, dt);
        vf_apply<2>(S, tid, S->symid, b1, b2, b3, gvec, dt);
    }

    // final readout (index NW)
    if (tid < 4) {
        float acc = br[tid] + shiftv;
        #pragma unroll 8
        for (int a = 0; a < 64; a++) acc += Wr[tid * 64 + a] * S->sy[a];
        out[b * (NW + 1) * OUTD + NW * OUTD + tid] = acc;
    }
}

extern "C" void kernel_launch(void* const* d_in, const int* in_sizes, int n_in,
                              void* d_out, int out_size) {
    (void)in_sizes; (void)n_in; (void)out_size;
    const size_t smem = sizeof(Smem);
    cudaFuncSetAttribute(ncde_kernel, cudaFuncAttributeMaxDynamicSharedMemorySize, (int)smem);
    ncde_kernel<<<BD, NTH, smem>>>(
        (const float*)d_in[0],
        (const float*)d_in[1], (const float*)d_in[2],
        (const float*)d_in[3], (const float*)d_in[4],
        (const float*)d_in[5], (const float*)d_in[6],
        (const float*)d_in[7], (const float*)d_in[8],
        (const float*)d_in[9], (const float*)d_in[10],
        (const float*)d_in[11], (const float*)d_in[12],
        (const float*)d_in[13],
        (float*)d_out);
}